// round 17
// baseline (speedup 1.0000x reference)
#include <cuda_runtime.h>
#include <cuda_fp16.h>
#include <mma.h>
#include <cstdint>

using namespace nvcuda;

#define BB 8
#define CIN 67
#define C2 128
#define CO 64
#define NN 16384
#define EPSV 1e-5f

#define KP 80        // padded K (67 data + bias row 67 + zeros to 80)
#define X_LD 88      // weight smem leading dim (halfs), [o][k]
#define XN_LD 264    // xkn leading dim (256 n + 8), [k][n]
#define KV_LD 264    // kf/vf leading dim
#define Q2_LD 152    // pass2 staging/mh leading dim (144 + 8)
#define TNS 256      // n super-tile
#define NV4 9
#define TOT4 (CIN * (TNS / 4))   // 4288

// pass1 smem byte offsets
#define P1_XK 0          // 80*264*2  = 42240
#define P1_WK 42240      // 22528
#define P1_WV 64768      // 22528
#define P1_KF 87296      // 67584
#define P1_VF 154880     // 67584
#define P1_TOTAL 222464
// pass2 smem byte offsets
#define P2_XK 0          // 42240
#define P2_WQ 42240      // 22528
#define P2_MH 64768      // 19456
#define P2_QS 84224      // 77824
#define P2_TOTAL 162048

#define P1_GRID 128
#define P2_GRID 128

// ---------------- device scratch ----------------
__device__ __align__(16) __half g_Wqh[C2 * X_LD];
__device__ __align__(16) __half g_Wkh[C2 * X_LD];
__device__ __align__(16) __half g_Wvh[C2 * X_LD];
__device__ float g_Wf[CO][C2];
__device__ float g_bf[CO];
__device__ float g_M[BB][CO][C2];            // (Wf . kv^T) / 64
__device__ float g_kvpart[P1_GRID][C2 * C2];

// relu on an f16 accumulator fragment, in place
template <typename FragH>
__device__ __forceinline__ void relu_h(FragH& h) {
    const __half z = __float2half(0.0f);
#pragma unroll
    for (int i = 0; i < h.num_elements; ++i) h.x[i] = __hmax(h.x[i], z);
}

__device__ __forceinline__ void load_x_tile(const float* __restrict__ xb, int nbase,
                                            __half* __restrict__ xkn, int tid) {
#pragma unroll
    for (int j = 0; j < NV4; ++j) {
        int i = tid + j * 512;
        if (i < TOT4) {
            int c = i >> 6, n4 = (i & 63) << 2;
            const float4 v = *reinterpret_cast<const float4*>(xb + (size_t)c * NN + nbase + n4);
            *reinterpret_cast<__half2*>(xkn + c * XN_LD + n4)     = __floats2half2_rn(v.x, v.y);
            *reinterpret_cast<__half2*>(xkn + c * XN_LD + n4 + 2) = __floats2half2_rn(v.z, v.w);
        }
    }
}

__device__ __forceinline__ void prefetch_regs(const float* __restrict__ xb, int nbase,
                                              float4* __restrict__ buf, int tid) {
#pragma unroll
    for (int j = 0; j < NV4; ++j) {
        int i = tid + j * 512;
        if (i < TOT4) {
            int c = i >> 6, n4 = (i & 63) << 2;
            buf[j] = *reinterpret_cast<const float4*>(xb + (size_t)c * NN + nbase + n4);
        }
    }
}

__device__ __forceinline__ void store_regs(const float4* __restrict__ buf,
                                           __half* __restrict__ xkn, int tid) {
#pragma unroll
    for (int j = 0; j < NV4; ++j) {
        int i = tid + j * 512;
        if (i < TOT4) {
            int c = i >> 6, n4 = (i & 63) << 2;
            *reinterpret_cast<__half2*>(xkn + c * XN_LD + n4)     = __floats2half2_rn(buf[j].x, buf[j].y);
            *reinterpret_cast<__half2*>(xkn + c * XN_LD + n4 + 2) = __floats2half2_rn(buf[j].z, buf[j].w);
        }
    }
}

// ---------------- prep (16 blocks) ----------------
__global__ void prep_kernel(const float* __restrict__ Wq, const float* __restrict__ Wk,
                            const float* __restrict__ Wv, const float* __restrict__ Wf,
                            const float* __restrict__ bnq, const float* __restrict__ bnk,
                            const float* __restrict__ bnv, const float* __restrict__ bnf) {
    __shared__ float sq[C2], sk[C2], sv[C2], shq[C2], shk[C2], shv[C2], sf[CO];
    int tid = threadIdx.x;
    if (tid < C2) {
        float s;
        s = bnq[tid] * rsqrtf(bnq[3 * C2 + tid] + EPSV); sq[tid] = s; shq[tid] = bnq[C2 + tid] - bnq[2 * C2 + tid] * s;
        s = bnk[tid] * rsqrtf(bnk[3 * C2 + tid] + EPSV); sk[tid] = s; shk[tid] = bnk[C2 + tid] - bnk[2 * C2 + tid] * s;
        s = bnv[tid] * rsqrtf(bnv[3 * C2 + tid] + EPSV); sv[tid] = s; shv[tid] = bnv[C2 + tid] - bnv[2 * C2 + tid] * s;
    }
    if (tid < CO) {
        float s = bnf[tid] * rsqrtf(bnf[3 * CO + tid] + EPSV);
        sf[tid] = s;
        if (blockIdx.x == 0) g_bf[tid] = bnf[CO + tid] - bnf[2 * CO + tid] * s;
    }
    __syncthreads();
    for (int i = blockIdx.x * 256 + tid; i < C2 * X_LD; i += gridDim.x * 256) {
        int o = i / X_LD, k = i % X_LD;
        float q = 0.f, kk = 0.f, v = 0.f;
        if (k < CIN) {
            q = Wq[o * CIN + k] * sq[o];
            kk = Wk[o * CIN + k] * sk[o];
            v = Wv[o * CIN + k] * sv[o];
        } else if (k == CIN) {
            q = shq[o]; kk = shk[o]; v = shv[o];
        }
        g_Wqh[i] = __float2half(q);
        g_Wkh[i] = __float2half(kk);
        g_Wvh[i] = __float2half(v);
    }
    for (int i = blockIdx.x * 256 + tid; i < CO * C2; i += gridDim.x * 256) {
        int o = i >> 7;
        g_Wf[0][i] = Wf[i] * sf[o];
    }
}

// ---------------- pass 1: merged k+v GEMM (f16 acc) + kv-outer (f32 acc) ----------------
__global__ void __launch_bounds__(512, 1) pass1_kernel(const float* __restrict__ x) {
    extern __shared__ char sm[];
    __half* xkn = (__half*)(sm + P1_XK);   // [k(80)][n(256)]
    __half* wk = (__half*)(sm + P1_WK);
    __half* wv = (__half*)(sm + P1_WV);
    __half* kf = (__half*)(sm + P1_KF);    // [c][n] ld KV_LD
    __half* vf = (__half*)(sm + P1_VF);

    const int tid = threadIdx.x, w = tid >> 5;
    const int b = blockIdx.x >> 4, split = blockIdx.x & 15;
    const float* xb = x + (size_t)b * CIN * NN;
    const int m0 = (w >> 2) * 32, nw = (w & 3) * 32;

    for (int i = tid * 4; i < C2 * X_LD; i += 512 * 4) {
        *reinterpret_cast<uint2*>(wk + i) = *reinterpret_cast<const uint2*>(g_Wkh + i);
        *reinterpret_cast<uint2*>(wv + i) = *reinterpret_cast<const uint2*>(g_Wvh + i);
    }
    for (int n = tid; n < TNS; n += 512) {
        xkn[CIN * XN_LD + n] = __float2half(1.0f);
#pragma unroll
        for (int k = CIN + 1; k < KP; ++k) xkn[k * XN_LD + n] = __float2half(0.0f);
    }

    wmma::fragment<wmma::accumulator, 16, 16, 16, float> kvacc[2][2];
#pragma unroll
    for (int mi = 0; mi < 2; ++mi)
#pragma unroll
        for (int ni = 0; ni < 2; ++ni) wmma::fill_fragment(kvacc[mi][ni], 0.0f);

    load_x_tile(xb, split * 1024, xkn, tid);
    __syncthreads();

    for (int t = 0; t < 4; ++t) {
        // ---- phase A: k and v GEMMs merged, f16 accumulators, shared B fragments ----
#pragma unroll
        for (int hn = 0; hn < 2; ++hn) {
            const int n0 = hn * 128 + nw;
            wmma::fragment<wmma::accumulator, 16, 16, 16, __half> acck[2][2], accv[2][2];
#pragma unroll
            for (int mi = 0; mi < 2; ++mi)
#pragma unroll
                for (int ni = 0; ni < 2; ++ni) {
                    wmma::fill_fragment(acck[mi][ni], __float2half(0.0f));
                    wmma::fill_fragment(accv[mi][ni], __float2half(0.0f));
                }
#pragma unroll
            for (int kk = 0; kk < KP / 16; ++kk) {
                wmma::fragment<wmma::matrix_a, 16, 16, 16, __half, wmma::row_major> afk[2], afv[2];
                wmma::fragment<wmma::matrix_b, 16, 16, 16, __half, wmma::row_major> bf[2];
#pragma unroll
                for (int mi = 0; mi < 2; ++mi) {
                    wmma::load_matrix_sync(afk[mi], wk + (m0 + mi * 16) * X_LD + kk * 16, X_LD);
                    wmma::load_matrix_sync(afv[mi], wv + (m0 + mi * 16) * X_LD + kk * 16, X_LD);
                }
#pragma unroll
                for (int ni = 0; ni < 2; ++ni)
                    wmma::load_matrix_sync(bf[ni], xkn + kk * 16 * XN_LD + n0 + ni * 16, XN_LD);
#pragma unroll
                for (int mi = 0; mi < 2; ++mi)
#pragma unroll
                    for (int ni = 0; ni < 2; ++ni) {
                        wmma::mma_sync(acck[mi][ni], afk[mi], bf[ni], acck[mi][ni]);
                        wmma::mma_sync(accv[mi][ni], afv[mi], bf[ni], accv[mi][ni]);
                    }
            }
#pragma unroll
            for (int mi = 0; mi < 2; ++mi)
#pragma unroll
                for (int ni = 0; ni < 2; ++ni) {
                    relu_h(acck[mi][ni]);
                    wmma::store_matrix_sync(kf + (m0 + mi * 16) * KV_LD + n0 + ni * 16, acck[mi][ni], KV_LD, wmma::mem_row_major);
                    relu_h(accv[mi][ni]);
                    wmma::store_matrix_sync(vf + (m0 + mi * 16) * KV_LD + n0 + ni * 16, accv[mi][ni], KV_LD, wmma::mem_row_major);
                }
        }
        __syncthreads();

        // ---- phase B: prefetch t+1 (regs) + kv-outer MMAs (f32 acc) + store xkn ----
        float4 buf[NV4];
        if (t < 3) prefetch_regs(xb, split * 1024 + (t + 1) * TNS, buf, tid);

#pragma unroll
        for (int kk = 0; kk < TNS / 16; ++kk) {
            wmma::fragment<wmma::matrix_a, 16, 16, 16, __half, wmma::row_major> af[2];
            wmma::fragment<wmma::matrix_b, 16, 16, 16, __half, wmma::col_major> bf[2];
#pragma unroll
            for (int mi = 0; mi < 2; ++mi)
                wmma::load_matrix_sync(af[mi], kf + (m0 + mi * 16) * KV_LD + kk * 16, KV_LD);
#pragma unroll
            for (int ni = 0; ni < 2; ++ni)
                wmma::load_matrix_sync(bf[ni], vf + (nw + ni * 16) * KV_LD + kk * 16, KV_LD);
#pragma unroll
            for (int mi = 0; mi < 2; ++mi)
#pragma unroll
                for (int ni = 0; ni < 2; ++ni) wmma::mma_sync(kvacc[mi][ni], af[mi], bf[ni], kvacc[mi][ni]);
        }

        if (t < 3) store_regs(buf, xkn, tid);
        __syncthreads();
    }

    float* part = g_kvpart[blockIdx.x];
#pragma unroll
    for (int mi = 0; mi < 2; ++mi)
#pragma unroll
        for (int ni = 0; ni < 2; ++ni)
            wmma::store_matrix_sync(part + (m0 + mi * 16) * C2 + nw + ni * 16, kvacc[mi][ni], C2, wmma::mem_row_major);
}

// ---------------- reduce kv partials + form M = (Wf . kv^T)/64 ----------------
__global__ void mkernel(void) {
    __shared__ float kvs[16 * C2];
    const int b = blockIdx.x >> 3, slice = blockIdx.x & 7;
    const int tid = threadIdx.x;
    for (int i = tid; i < 16 * C2; i += 256) {
        int cl = i >> 7, d = i & 127;
        int c = slice * 16 + cl;
        float s = 0.f;
#pragma unroll
        for (int p = 0; p < 16; ++p) s += g_kvpart[b * 16 + p][c * C2 + d];
        kvs[i] = s;
    }
    __syncthreads();
    for (int i = tid; i < CO * 16; i += 256) {
        int o = i >> 4, cl = i & 15;
        float acc = 0.f;
#pragma unroll 8
        for (int d = 0; d < C2; ++d) acc = fmaf(g_Wf[o][d], kvs[cl * C2 + d], acc);
        g_M[b][o][slice * 16 + cl] = acc * (1.f / 64.f);
    }
}

// ---------------- pass 2: warp-fused q(f16 acc)->out(f32 acc), bias column, direct stores ----------------
__global__ void __launch_bounds__(512, 1) pass2_kernel(const float* __restrict__ x, float* __restrict__ out) {
    extern __shared__ char sm[];
    __half* xkn = (__half*)(sm + P2_XK);   // [k(80)][n(256)]
    __half* wq = (__half*)(sm + P2_WQ);    // [c][k] ld X_LD
    __half* mh = (__half*)(sm + P2_MH);    // [o][c(144+pad)] ld Q2_LD
    __half* qs = (__half*)(sm + P2_QS);    // staging [256 rows][Q2_LD]

    const int tid = threadIdx.x, w = tid >> 5;
    const int b = blockIdx.x >> 4, split = blockIdx.x & 15;
    const float* xb = x + (size_t)b * CIN * NN;
    const int ng = w * 16;
    __half* sQ = qs + ng * Q2_LD;

    for (int i = tid * 4; i < C2 * X_LD; i += 512 * 4)
        *reinterpret_cast<uint2*>(wq + i) = *reinterpret_cast<const uint2*>(g_Wqh + i);
    for (int i = tid; i < CO * Q2_LD; i += 512) {
        int o = i / Q2_LD, c = i % Q2_LD;
        float v = (c < C2) ? g_M[b][o][c] : (c == C2 ? g_bf[o] * (1.f / 64.f) : 0.f);
        mh[i] = __float2half(v);
    }
    for (int i = tid; i < TNS * 24; i += 512) {
        int row = i / 24, c = C2 + i % 24;
        qs[row * Q2_LD + c] = __float2half(c == C2 ? 1.0f : 0.0f);
    }
    for (int n = tid; n < TNS; n += 512) {
        xkn[CIN * XN_LD + n] = __float2half(1.0f);
#pragma unroll
        for (int k = CIN + 1; k < KP; ++k) xkn[k * XN_LD + n] = __float2half(0.0f);
    }

    load_x_tile(xb, split * 1024, xkn, tid);
    __syncthreads();

    for (int t = 0; t < 4; ++t) {
        const int nbase = split * 1024 + t * TNS;

        // ---- q GEMM: D[16n][128c], f16 accumulators ----
        {
            wmma::fragment<wmma::accumulator, 16, 16, 16, __half> acc[8];
#pragma unroll
            for (int ni = 0; ni < 8; ++ni) wmma::fill_fragment(acc[ni], __float2half(0.0f));
#pragma unroll
            for (int kk = 0; kk < KP / 16; ++kk) {
                wmma::fragment<wmma::matrix_a, 16, 16, 16, __half, wmma::col_major> af;
                wmma::load_matrix_sync(af, xkn + kk * 16 * XN_LD + ng, XN_LD);
#pragma unroll
                for (int ni = 0; ni < 8; ++ni) {
                    wmma::fragment<wmma::matrix_b, 16, 16, 16, __half, wmma::col_major> bf;
                    wmma::load_matrix_sync(bf, wq + (ni * 16) * X_LD + kk * 16, X_LD);
                    wmma::mma_sync(acc[ni], af, bf, acc[ni]);
                }
            }
#pragma unroll
            for (int ni = 0; ni < 8; ++ni) {
                relu_h(acc[ni]);
                wmma::store_matrix_sync(sQ + ni * 16, acc[ni], Q2_LD, wmma::mem_row_major);
            }
        }
        __syncwarp();

        // ---- prefetch next tile ----
        float4 buf[NV4];
        if (t < 3) prefetch_regs(xb, nbase + TNS, buf, tid);

        // ---- out GEMM: D[16n][64o], K=144 (bias column), f32 acc, direct gmem store ----
        {
            wmma::fragment<wmma::accumulator, 16, 16, 16, float> oacc[4];
#pragma unroll
            for (int oi = 0; oi < 4; ++oi) wmma::fill_fragment(oacc[oi], 0.0f);
#pragma unroll
            for (int kk = 0; kk < 9; ++kk) {
                wmma::fragment<wmma::matrix_a, 16, 16, 16, __half, wmma::row_major> af;
                wmma::load_matrix_sync(af, sQ + kk * 16, Q2_LD);
#pragma unroll
                for (int oi = 0; oi < 4; ++oi) {
                    wmma::fragment<wmma::matrix_b, 16, 16, 16, __half, wmma::col_major> bf;
                    wmma::load_matrix_sync(bf, mh + (oi * 16) * Q2_LD + kk * 16, Q2_LD);
                    wmma::mma_sync(oacc[oi], af, bf, oacc[oi]);
                }
            }
#pragma unroll
            for (int oi = 0; oi < 4; ++oi) {
#pragma unroll
                for (int e = 0; e < oacc[oi].num_elements; ++e)
                    oacc[oi].x[e] = fmaxf(oacc[oi].x[e] * 64.0f, 0.0f);
                wmma::store_matrix_sync(out + (size_t)(b * CO + oi * 16) * NN + nbase + ng,
                                        oacc[oi], NN, wmma::mem_col_major);
            }
        }
        __syncthreads();

        if (t < 3) store_regs(buf, xkn, tid);
        __syncthreads();
    }
}

// ---------------- launch ----------------
extern "C" void kernel_launch(void* const* d_in, const int* in_sizes, int n_in,
                              void* d_out, int out_size) {
    const float* x   = (const float*)d_in[0];
    const float* Wq  = (const float*)d_in[1];
    const float* Wk  = (const float*)d_in[2];
    const float* Wv  = (const float*)d_in[3];
    const float* Wf  = (const float*)d_in[4];
    const float* bnq = (const float*)d_in[5];
    const float* bnk = (const float*)d_in[6];
    const float* bnv = (const float*)d_in[7];
    const float* bnf = (const float*)d_in[8];
    float* out = (float*)d_out;

    cudaFuncSetAttribute(pass1_kernel, cudaFuncAttributeMaxDynamicSharedMemorySize, P1_TOTAL);
    cudaFuncSetAttribute(pass2_kernel, cudaFuncAttributeMaxDynamicSharedMemorySize, P2_TOTAL);

    prep_kernel<<<16, 256>>>(Wq, Wk, Wv, Wf, bnq, bnk, bnv, bnf);
    pass1_kernel<<<P1_GRID, 512, P1_TOTAL>>>(x);
    mkernel<<<64, 256>>>();
    pass2_kernel<<<P2_GRID, 512, P2_TOTAL>>>(x, out);
}